// round 1
// baseline (speedup 1.0000x reference)
#include <cuda_runtime.h>
#include <cstdint>

#define D 128
#define N_NODES_MAX 100000
#define GEMM_TM 32

// Scratch (allocation-free rule: __device__ globals)
__device__ float g_h[(size_t)N_NODES_MAX * D];    // linear output, later reused for LN output
__device__ float g_acc[(size_t)N_NODES_MAX * D];  // segment-sum accumulator

// ---------------------------------------------------------------------------
// 0) zero accumulator
// ---------------------------------------------------------------------------
__global__ void zero_acc_kernel(int n4) {
    float4* p = (float4*)g_acc;
    float4 z = make_float4(0.f, 0.f, 0.f, 0.f);
    int i = blockIdx.x * blockDim.x + threadIdx.x;
    int stride = gridDim.x * blockDim.x;
    for (; i < n4; i += stride) p[i] = z;
}

// ---------------------------------------------------------------------------
// 1) h = emb @ W + bias        (n x 128) = (n x 128)(128 x 128)
//    128 threads/block, thread j owns output column j, 32 rows per block.
//    emb tile staged in shared (16KB); W streamed through L1 (64KB resident).
// ---------------------------------------------------------------------------
__global__ void gemm_kernel(const float* __restrict__ emb,
                            const float* __restrict__ W,
                            const float* __restrict__ bias,
                            int n) {
    __shared__ float4 s_e[GEMM_TM * 32];   // 32 rows x 128 floats = 16KB
    const int tid = threadIdx.x;           // 0..127
    const int base = blockIdx.x * GEMM_TM;

    const float4* e4 = (const float4*)emb;
    #pragma unroll
    for (int i = tid; i < GEMM_TM * 32; i += 128) {
        int r = i >> 5;
        int row = base + r;
        s_e[i] = (row < n) ? __ldg(e4 + (size_t)row * 32 + (i & 31))
                           : make_float4(0.f, 0.f, 0.f, 0.f);
    }
    __syncthreads();

    float acc[GEMM_TM];
    #pragma unroll
    for (int r = 0; r < GEMM_TM; r++) acc[r] = 0.f;

    const int j = tid;
    #pragma unroll 8
    for (int k = 0; k < D; k += 4) {
        float w0 = __ldg(W + (k + 0) * D + j);
        float w1 = __ldg(W + (k + 1) * D + j);
        float w2 = __ldg(W + (k + 2) * D + j);
        float w3 = __ldg(W + (k + 3) * D + j);
        #pragma unroll
        for (int r = 0; r < GEMM_TM; r++) {
            float4 e = s_e[(r << 5) + (k >> 2)];
            acc[r] = fmaf(e.x, w0, acc[r]);
            acc[r] = fmaf(e.y, w1, acc[r]);
            acc[r] = fmaf(e.z, w2, acc[r]);
            acc[r] = fmaf(e.w, w3, acc[r]);
        }
    }

    const float b = __ldg(bias + j);
    #pragma unroll
    for (int r = 0; r < GEMM_TM; r++) {
        int row = base + r;
        if (row < n) g_h[(size_t)row * D + j] = acc[r] + b;
    }
}

// ---------------------------------------------------------------------------
// 2) SpMM scatter: acc[rows[e]] += vals[e] * h[cols[e]]
//    warp per edge; vectorized fp32 reduction (red.global.add.v4.f32, sm_90+)
// ---------------------------------------------------------------------------
__device__ __forceinline__ void red_add_v4(float* p, float a, float b, float c, float d) {
    asm volatile("red.global.add.v4.f32 [%0], {%1, %2, %3, %4};"
                 :: "l"(p), "f"(a), "f"(b), "f"(c), "f"(d)
                 : "memory");
}

__global__ void spmm_kernel(const float* __restrict__ vals,
                            const int* __restrict__ rows,
                            const int* __restrict__ cols,
                            int E) {
    int gtid = blockIdx.x * blockDim.x + threadIdx.x;
    int e = gtid >> 5;
    int lane = gtid & 31;
    if (e >= E) return;

    int   c = __ldg(cols + e);
    int   r = __ldg(rows + e);
    float v = __ldg(vals + e);

    float4 h4 = __ldg((const float4*)(g_h + (size_t)c * D) + lane);
    red_add_v4(g_acc + (size_t)r * D + lane * 4,
               v * h4.x, v * h4.y, v * h4.z, v * h4.w);
}

// ---------------------------------------------------------------------------
// 3) relu + LayerNorm; writes LN output into g_h (h no longer needed)
// ---------------------------------------------------------------------------
__global__ void ln_kernel(const float* __restrict__ gamma,
                          const float* __restrict__ beta,
                          int n) {
    int gtid = blockIdx.x * blockDim.x + threadIdx.x;
    int node = gtid >> 5;
    int lane = gtid & 31;
    if (node >= n) return;

    float4 a = ((const float4*)(g_acc + (size_t)node * D))[lane];
    a.x = fmaxf(a.x, 0.f);
    a.y = fmaxf(a.y, 0.f);
    a.z = fmaxf(a.z, 0.f);
    a.w = fmaxf(a.w, 0.f);

    float s  = a.x + a.y + a.z + a.w;
    float ss = a.x * a.x + a.y * a.y + a.z * a.z + a.w * a.w;
    #pragma unroll
    for (int o = 16; o > 0; o >>= 1) {
        s  += __shfl_xor_sync(0xffffffffu, s, o);
        ss += __shfl_xor_sync(0xffffffffu, ss, o);
    }
    const float inv_d = 1.f / 128.f;
    float mu  = s * inv_d;
    float var = ss * inv_d - mu * mu;
    float rs  = rsqrtf(var + 1e-5f);

    float4 g = __ldg((const float4*)gamma + lane);
    float4 b = __ldg((const float4*)beta + lane);
    float4 o4;
    o4.x = (a.x - mu) * rs * g.x + b.x;
    o4.y = (a.y - mu) * rs * g.y + b.y;
    o4.z = (a.z - mu) * rs * g.z + b.z;
    o4.w = (a.w - mu) * rs * g.w + b.w;

    ((float4*)(g_h + (size_t)node * D))[lane] = o4;
}

// ---------------------------------------------------------------------------
// 4) masked gather: out[b] = select(x[b] in [1,n]) ? ln[x[b]-1] : 0
// ---------------------------------------------------------------------------
__global__ void gather_kernel(const int* __restrict__ x,
                              float* __restrict__ out,
                              int B, int n) {
    int gtid = blockIdx.x * blockDim.x + threadIdx.x;
    int b = gtid >> 5;
    int lane = gtid & 31;
    if (b >= B) return;

    int xv = __ldg(x + b);
    float4 o = make_float4(0.f, 0.f, 0.f, 0.f);
    if (xv >= 1 && xv <= n)
        o = __ldg((const float4*)(g_h + (size_t)(xv - 1) * D) + lane);
    ((float4*)(out + (size_t)b * D))[lane] = o;
}

// ---------------------------------------------------------------------------
// launch
// ---------------------------------------------------------------------------
extern "C" void kernel_launch(void* const* d_in, const int* in_sizes, int n_in,
                              void* d_out, int out_size) {
    const int*   x     = (const int*)d_in[0];
    const float* emb   = (const float*)d_in[1];
    const float* W     = (const float*)d_in[2];
    const float* bias  = (const float*)d_in[3];
    const float* vals  = (const float*)d_in[4];
    const int*   rows  = (const int*)d_in[5];
    const int*   cols  = (const int*)d_in[6];
    const float* gamma = (const float*)d_in[7];
    const float* beta  = (const float*)d_in[8];
    float* out = (float*)d_out;

    const int B = in_sizes[0];
    const int n = in_sizes[1] / D;
    const int E = in_sizes[4];

    // 0) zero accumulator
    zero_acc_kernel<<<2048, 256>>>(n * (D / 4));

    // 1) dense linear
    int gemm_blocks = (n + GEMM_TM - 1) / GEMM_TM;
    gemm_kernel<<<gemm_blocks, 128>>>(emb, W, bias, n);

    // 2) sparse scatter-add (warp per edge)
    long long spmm_threads = (long long)E * 32;
    int spmm_blocks = (int)((spmm_threads + 255) / 256);
    spmm_kernel<<<spmm_blocks, 256>>>(vals, rows, cols, E);

    // 3) relu + LayerNorm (warp per node)
    long long ln_threads = (long long)n * 32;
    int ln_blocks = (int)((ln_threads + 255) / 256);
    ln_kernel<<<ln_blocks, 256>>>(gamma, beta, n);

    // 4) masked gather (warp per batch row)
    long long gb_threads = (long long)B * 32;
    int gb_blocks = (int)((gb_threads + 255) / 256);
    gather_kernel<<<gb_blocks, 256>>>(x, out, B, n);
}

// round 4
// speedup vs baseline: 1.2636x; 1.2636x over previous
#include <cuda_runtime.h>
#include <cstdint>

#define D 128
#define NN_MAX 100000
#define E_MAX  1600000
#define GEMM_TM 32
#define SCAN_BLK 1024
#define MAX_SCAN_BLOCKS 128

// ---------------- device scratch (allocation-free rule) ----------------
__device__ float g_h [(size_t)NN_MAX * D];    // GEMM output h
__device__ float g_ln[(size_t)NN_MAX * D];    // LN output
__device__ int   g_cnt[NN_MAX];
__device__ int   g_off[NN_MAX + 1];
__device__ int   g_cur[NN_MAX];
__device__ int   g_scol[E_MAX];
__device__ float g_sval[E_MAX];
__device__ int   g_bsum[MAX_SCAN_BLOCKS];

// ---------------------------------------------------------------------------
// CSR build: count -> scan -> scatter
// ---------------------------------------------------------------------------
__global__ void zero_cnt_kernel(int n) {
    int i = blockIdx.x * blockDim.x + threadIdx.x;
    if (i < n) g_cnt[i] = 0;
}

__global__ void count_kernel(const int* __restrict__ rows, int E) {
    int i = blockIdx.x * blockDim.x + threadIdx.x;
    int stride = gridDim.x * blockDim.x;
    for (; i < E; i += stride) atomicAdd(&g_cnt[__ldg(rows + i)], 1);
}

// per-block exclusive scan over SCAN_BLK elements
__global__ void scan1_kernel(int n) {
    __shared__ int s[SCAN_BLK];
    int t = threadIdx.x;
    int i = blockIdx.x * SCAN_BLK + t;
    int v = (i < n) ? g_cnt[i] : 0;
    s[t] = v;
    __syncthreads();
    #pragma unroll
    for (int off = 1; off < SCAN_BLK; off <<= 1) {
        int add = (t >= off) ? s[t - off] : 0;
        __syncthreads();
        s[t] += add;
        __syncthreads();
    }
    if (i < n) g_off[i] = s[t] - v;           // exclusive within block
    if (t == SCAN_BLK - 1) g_bsum[blockIdx.x] = s[t];
}

// single-block exclusive scan of block sums
__global__ void scan2_kernel(int nb) {
    __shared__ int s[MAX_SCAN_BLOCKS];
    int t = threadIdx.x;
    int v = (t < nb) ? g_bsum[t] : 0;
    s[t] = v;
    __syncthreads();
    #pragma unroll
    for (int off = 1; off < MAX_SCAN_BLOCKS; off <<= 1) {
        int add = (t >= off) ? s[t - off] : 0;
        __syncthreads();
        s[t] += add;
        __syncthreads();
    }
    if (t < nb) g_bsum[t] = s[t] - v;
}

__global__ void scan3_kernel(int n, int E) {
    int i = blockIdx.x * blockDim.x + threadIdx.x;
    if (i < n) {
        int o = g_off[i] + g_bsum[i / SCAN_BLK];
        g_off[i] = o;
        g_cur[i] = o;
    }
    if (i == 0) g_off[n] = E;
}

__global__ void scatter_kernel(const int* __restrict__ rows,
                               const int* __restrict__ cols,
                               const float* __restrict__ vals,
                               int E) {
    int i = blockIdx.x * blockDim.x + threadIdx.x;
    int stride = gridDim.x * blockDim.x;
    for (; i < E; i += stride) {
        int r = __ldg(rows + i);
        int p = atomicAdd(&g_cur[r], 1);
        g_scol[p] = __ldg(cols + i);
        g_sval[p] = __ldg(vals + i);
    }
}

// ---------------------------------------------------------------------------
// 1) h = emb @ W + bias
// ---------------------------------------------------------------------------
__global__ void gemm_kernel(const float* __restrict__ emb,
                            const float* __restrict__ W,
                            const float* __restrict__ bias,
                            int n) {
    __shared__ float4 s_e[GEMM_TM * 32];
    const int tid = threadIdx.x;          // 0..127
    const int base = blockIdx.x * GEMM_TM;

    const float4* e4 = (const float4*)emb;
    #pragma unroll
    for (int i = tid; i < GEMM_TM * 32; i += 128) {
        int row = base + (i >> 5);
        s_e[i] = (row < n) ? __ldg(e4 + (size_t)row * 32 + (i & 31))
                           : make_float4(0.f, 0.f, 0.f, 0.f);
    }
    __syncthreads();

    float acc[GEMM_TM];
    #pragma unroll
    for (int r = 0; r < GEMM_TM; r++) acc[r] = 0.f;

    const int j = tid;
    #pragma unroll 8
    for (int k = 0; k < D; k += 4) {
        float w0 = __ldg(W + (k + 0) * D + j);
        float w1 = __ldg(W + (k + 1) * D + j);
        float w2 = __ldg(W + (k + 2) * D + j);
        float w3 = __ldg(W + (k + 3) * D + j);
        #pragma unroll
        for (int r = 0; r < GEMM_TM; r++) {
            float4 e = s_e[(r << 5) + (k >> 2)];
            acc[r] = fmaf(e.x, w0, acc[r]);
            acc[r] = fmaf(e.y, w1, acc[r]);
            acc[r] = fmaf(e.z, w2, acc[r]);
            acc[r] = fmaf(e.w, w3, acc[r]);
        }
    }

    const float b = __ldg(bias + j);
    #pragma unroll
    for (int r = 0; r < GEMM_TM; r++) {
        int row = base + r;
        if (row < n) g_h[(size_t)row * D + j] = acc[r] + b;
    }
}

// ---------------------------------------------------------------------------
// 2) fused SpMM (warp per row, register accumulation) + ReLU + LayerNorm
// ---------------------------------------------------------------------------
__global__ void spmm_ln_kernel(const float* __restrict__ gamma,
                               const float* __restrict__ beta,
                               int n) {
    int gtid = blockIdx.x * blockDim.x + threadIdx.x;
    int row = gtid >> 5;
    int lane = gtid & 31;
    if (row >= n) return;

    int s   = g_off[row];
    int end = g_off[row + 1];

    float4 acc = make_float4(0.f, 0.f, 0.f, 0.f);
    for (int base = s; base < end; base += 32) {
        int m = min(32, end - base);
        int c = 0;
        float v = 0.f;
        if (lane < m) {
            c = g_scol[base + lane];
            v = g_sval[base + lane];
        }
        for (int j = 0; j < m; j++) {
            int   cj = __shfl_sync(0xffffffffu, c, j);
            float vj = __shfl_sync(0xffffffffu, v, j);
            float4 h4 = __ldg((const float4*)(g_h + (size_t)cj * D) + lane);
            acc.x = fmaf(vj, h4.x, acc.x);
            acc.y = fmaf(vj, h4.y, acc.y);
            acc.z = fmaf(vj, h4.z, acc.z);
            acc.w = fmaf(vj, h4.w, acc.w);
        }
    }

    // ReLU
    acc.x = fmaxf(acc.x, 0.f);
    acc.y = fmaxf(acc.y, 0.f);
    acc.z = fmaxf(acc.z, 0.f);
    acc.w = fmaxf(acc.w, 0.f);

    // LayerNorm over 128
    float sum = acc.x + acc.y + acc.z + acc.w;
    float ssq = acc.x * acc.x + acc.y * acc.y + acc.z * acc.z + acc.w * acc.w;
    #pragma unroll
    for (int o = 16; o > 0; o >>= 1) {
        sum += __shfl_xor_sync(0xffffffffu, sum, o);
        ssq += __shfl_xor_sync(0xffffffffu, ssq, o);
    }
    const float inv_d = 1.f / 128.f;
    float mu  = sum * inv_d;
    float var = ssq * inv_d - mu * mu;
    float rs  = rsqrtf(var + 1e-5f);

    float4 g = __ldg((const float4*)gamma + lane);
    float4 b = __ldg((const float4*)beta + lane);
    float4 o4;
    o4.x = (acc.x - mu) * rs * g.x + b.x;
    o4.y = (acc.y - mu) * rs * g.y + b.y;
    o4.z = (acc.z - mu) * rs * g.z + b.z;
    o4.w = (acc.w - mu) * rs * g.w + b.w;

    ((float4*)(g_ln + (size_t)row * D))[lane] = o4;
}

// ---------------------------------------------------------------------------
// 3) masked gather
// ---------------------------------------------------------------------------
__global__ void gather_kernel(const int* __restrict__ x,
                              float* __restrict__ out,
                              int B, int n) {
    int gtid = blockIdx.x * blockDim.x + threadIdx.x;
    int b = gtid >> 5;
    int lane = gtid & 31;
    if (b >= B) return;

    int xv = __ldg(x + b);
    float4 o = make_float4(0.f, 0.f, 0.f, 0.f);
    if (xv >= 1 && xv <= n)
        o = __ldg((const float4*)(g_ln + (size_t)(xv - 1) * D) + lane);
    ((float4*)(out + (size_t)b * D))[lane] = o;
}

// ---------------------------------------------------------------------------
// launch
// ---------------------------------------------------------------------------
extern "C" void kernel_launch(void* const* d_in, const int* in_sizes, int n_in,
                              void* d_out, int out_size) {
    const int*   x     = (const int*)d_in[0];
    const float* emb   = (const float*)d_in[1];
    const float* W     = (const float*)d_in[2];
    const float* bias  = (const float*)d_in[3];
    const float* vals  = (const float*)d_in[4];
    const int*   rows  = (const int*)d_in[5];
    const int*   cols  = (const int*)d_in[6];
    const float* gamma = (const float*)d_in[7];
    const float* beta  = (const float*)d_in[8];
    float* out = (float*)d_out;

    const int B = in_sizes[0];
    const int n = in_sizes[1] / D;
    const int E = in_sizes[4];

    // CSR build
    zero_cnt_kernel<<<(n + 1023) / 1024, 1024>>>(n);
    count_kernel<<<1184, 256>>>(rows, E);
    int nb = (n + SCAN_BLK - 1) / SCAN_BLK;
    scan1_kernel<<<nb, SCAN_BLK>>>(n);
    scan2_kernel<<<1, MAX_SCAN_BLOCKS>>>(nb);
    scan3_kernel<<<(n + 255) / 256, 256>>>(n, E);
    scatter_kernel<<<1184, 256>>>(rows, cols, vals, E);

    // dense linear (independent of CSR build; h needed only by spmm)
    gemm_kernel<<<(n + GEMM_TM - 1) / GEMM_TM, 128>>>(emb, W, bias, n);

    // fused SpMM + ReLU + LN (warp per row)
    long long t2 = (long long)n * 32;
    spmm_ln_kernel<<<(int)((t2 + 255) / 256), 256>>>(gamma, beta, n);

    // masked gather
    long long t3 = (long long)B * 32;
    gather_kernel<<<(int)((t3 + 255) / 256), 256>>>(x, out, B, n);
}

// round 5
// speedup vs baseline: 1.7337x; 1.3720x over previous
#include <cuda_runtime.h>
#include <cstdint>

#define D 128
#define NN_MAX 100000
#define E_MAX  1600000
#define SCAN_BLK 1024
#define MAX_SCAN_BLOCKS 128
#define GEMM_BLK_M 128

// ---------------- device scratch (allocation-free rule) ----------------
__device__ float g_h [(size_t)NN_MAX * D];    // GEMM output h
__device__ float g_ln[(size_t)NN_MAX * D];    // LN output
__device__ int   g_cnt[NN_MAX];
__device__ int   g_off[NN_MAX + 1];
__device__ int   g_cur[NN_MAX];
__device__ int   g_scol[E_MAX];
__device__ float g_sval[E_MAX];
__device__ int   g_bsum[MAX_SCAN_BLOCKS];

// ---------------------------------------------------------------------------
// CSR build: count -> scan -> scatter
// ---------------------------------------------------------------------------
__global__ void zero_cnt_kernel(int n) {
    int i = blockIdx.x * blockDim.x + threadIdx.x;
    if (i < n) g_cnt[i] = 0;
}

__global__ void count_kernel(const int* __restrict__ rows, int E) {
    int i = blockIdx.x * blockDim.x + threadIdx.x;
    int stride = gridDim.x * blockDim.x;
    for (; i < E; i += stride) atomicAdd(&g_cnt[__ldg(rows + i)], 1);
}

__global__ void scan1_kernel(int n) {
    __shared__ int s[SCAN_BLK];
    int t = threadIdx.x;
    int i = blockIdx.x * SCAN_BLK + t;
    int v = (i < n) ? g_cnt[i] : 0;
    s[t] = v;
    __syncthreads();
    #pragma unroll
    for (int off = 1; off < SCAN_BLK; off <<= 1) {
        int add = (t >= off) ? s[t - off] : 0;
        __syncthreads();
        s[t] += add;
        __syncthreads();
    }
    if (i < n) g_off[i] = s[t] - v;
    if (t == SCAN_BLK - 1) g_bsum[blockIdx.x] = s[t];
}

__global__ void scan2_kernel(int nb) {
    __shared__ int s[MAX_SCAN_BLOCKS];
    int t = threadIdx.x;
    int v = (t < nb) ? g_bsum[t] : 0;
    s[t] = v;
    __syncthreads();
    #pragma unroll
    for (int off = 1; off < MAX_SCAN_BLOCKS; off <<= 1) {
        int add = (t >= off) ? s[t - off] : 0;
        __syncthreads();
        s[t] += add;
        __syncthreads();
    }
    if (t < nb) g_bsum[t] = s[t] - v;
}

__global__ void scan3_kernel(int n, int E) {
    int i = blockIdx.x * blockDim.x + threadIdx.x;
    if (i < n) {
        int o = g_off[i] + g_bsum[i / SCAN_BLK];
        g_off[i] = o;
        g_cur[i] = o;
    }
    if (i == 0) g_off[n] = E;
}

__global__ void scatter_kernel(const int* __restrict__ rows,
                               const int* __restrict__ cols,
                               const float* __restrict__ vals,
                               int E) {
    int i = blockIdx.x * blockDim.x + threadIdx.x;
    int stride = gridDim.x * blockDim.x;
    for (; i < E; i += stride) {
        int r = __ldg(rows + i);
        int p = atomicAdd(&g_cur[r], 1);
        g_scol[p] = __ldg(cols + i);
        g_sval[p] = __ldg(vals + i);
    }
}

// ---------------------------------------------------------------------------
// 1) h = emb @ W + bias  — tf32 tensor-core GEMM (mma.sync m16n8k8)
//    Block: 256 thr (8 warps), tile M=128 x N=128. W staged in 64KB dyn smem
//    as interleaved tf32 pairs (W[k][n], W[k+4][n]) at idx = s*512 + n*4 + t.
// ---------------------------------------------------------------------------
__device__ __forceinline__ uint32_t f2tf32(float f) {
    uint32_t u;
    asm("cvt.rna.tf32.f32 %0, %1;" : "=r"(u) : "f"(f));
    return u;
}

__global__ void __launch_bounds__(256, 2)
gemm_tc_kernel(const float* __restrict__ emb,
               const float* __restrict__ W,
               const float* __restrict__ bias,
               int n) {
    extern __shared__ float2 s_w[];        // 8192 float2 = 64KB
    const int tid  = threadIdx.x;
    const int lane = tid & 31;
    const int warp = tid >> 5;             // 0..7
    const int tg   = lane & 3;             // thread-in-group
    const int grp  = lane >> 2;            // 0..7

    // stage W as packed tf32 pairs
    #pragma unroll
    for (int i = tid; i < 8192; i += 256) {
        int s   = i >> 9;                  // kstep 0..15
        int rem = i & 511;
        int nn  = rem >> 2;                // 0..127
        int t   = rem & 3;                 // 0..3
        int k0  = s * 8 + t;
        float w0 = __ldg(W + k0 * D + nn);
        float w1 = __ldg(W + (k0 + 4) * D + nn);
        s_w[i] = make_float2(__uint_as_float(f2tf32(w0)), __uint_as_float(f2tf32(w1)));
    }
    __syncthreads();

    const int row0 = blockIdx.x * GEMM_BLK_M + warp * 16 + grp;
    const int row1 = row0 + 8;
    const bool v0 = row0 < n;
    const bool v1 = row1 < n;
    const float* a0p = emb + (size_t)(v0 ? row0 : 0) * D;
    const float* a1p = emb + (size_t)(v1 ? row1 : 0) * D;

    float c[16][4];
    #pragma unroll
    for (int nf = 0; nf < 16; nf++)
        c[nf][0] = c[nf][1] = c[nf][2] = c[nf][3] = 0.f;

    #pragma unroll
    for (int s = 0; s < 16; s++) {
        int k = s * 8 + tg;
        uint32_t a0 = 0, a1 = 0, a2 = 0, a3 = 0;
        if (v0) { a0 = f2tf32(__ldg(a0p + k)); a2 = f2tf32(__ldg(a0p + k + 4)); }
        if (v1) { a1 = f2tf32(__ldg(a1p + k)); a3 = f2tf32(__ldg(a1p + k + 4)); }

        const float2* wp = s_w + (s << 9) + (grp << 2) + tg;   // nn = grp (nf=0)
        #pragma unroll
        for (int nf = 0; nf < 16; nf++) {
            float2 b = wp[nf << 5];                            // nn += 8 per nf
            uint32_t b0 = __float_as_uint(b.x);
            uint32_t b1 = __float_as_uint(b.y);
            asm volatile(
                "mma.sync.aligned.m16n8k8.row.col.f32.tf32.tf32.f32 "
                "{%0,%1,%2,%3}, {%4,%5,%6,%7}, {%8,%9}, {%0,%1,%2,%3};"
                : "+f"(c[nf][0]), "+f"(c[nf][1]), "+f"(c[nf][2]), "+f"(c[nf][3])
                : "r"(a0), "r"(a1), "r"(a2), "r"(a3), "r"(b0), "r"(b1));
        }
    }

    // epilogue: add bias, store float2 pairs
    #pragma unroll
    for (int nf = 0; nf < 16; nf++) {
        int col = (nf << 3) + (tg << 1);
        float2 b2 = __ldg((const float2*)(bias + col));
        if (v0) {
            float2 o = make_float2(c[nf][0] + b2.x, c[nf][1] + b2.y);
            *(float2*)(g_h + (size_t)row0 * D + col) = o;
        }
        if (v1) {
            float2 o = make_float2(c[nf][2] + b2.x, c[nf][3] + b2.y);
            *(float2*)(g_h + (size_t)row1 * D + col) = o;
        }
    }
}

// ---------------------------------------------------------------------------
// 2) fused SpMM (warp per row, register accumulation) + ReLU + LayerNorm
// ---------------------------------------------------------------------------
__global__ void spmm_ln_kernel(const float* __restrict__ gamma,
                               const float* __restrict__ beta,
                               int n) {
    int gtid = blockIdx.x * blockDim.x + threadIdx.x;
    int row = gtid >> 5;
    int lane = gtid & 31;
    if (row >= n) return;

    int s   = g_off[row];
    int end = g_off[row + 1];

    float4 acc = make_float4(0.f, 0.f, 0.f, 0.f);
    for (int base = s; base < end; base += 32) {
        int m = min(32, end - base);
        int c = 0;
        float v = 0.f;
        if (lane < m) {
            c = g_scol[base + lane];
            v = g_sval[base + lane];
        }
        #pragma unroll 4
        for (int j = 0; j < m; j++) {
            int   cj = __shfl_sync(0xffffffffu, c, j);
            float vj = __shfl_sync(0xffffffffu, v, j);
            float4 h4 = __ldg((const float4*)(g_h + (size_t)cj * D) + lane);
            acc.x = fmaf(vj, h4.x, acc.x);
            acc.y = fmaf(vj, h4.y, acc.y);
            acc.z = fmaf(vj, h4.z, acc.z);
            acc.w = fmaf(vj, h4.w, acc.w);
        }
    }

    // ReLU
    acc.x = fmaxf(acc.x, 0.f);
    acc.y = fmaxf(acc.y, 0.f);
    acc.z = fmaxf(acc.z, 0.f);
    acc.w = fmaxf(acc.w, 0.f);

    // LayerNorm over 128
    float sum = acc.x + acc.y + acc.z + acc.w;
    float ssq = acc.x * acc.x + acc.y * acc.y + acc.z * acc.z + acc.w * acc.w;
    #pragma unroll
    for (int o = 16; o > 0; o >>= 1) {
        sum += __shfl_xor_sync(0xffffffffu, sum, o);
        ssq += __shfl_xor_sync(0xffffffffu, ssq, o);
    }
    const float inv_d = 1.f / 128.f;
    float mu  = sum * inv_d;
    float var = ssq * inv_d - mu * mu;
    float rs  = rsqrtf(var + 1e-5f);

    float4 g = __ldg((const float4*)gamma + lane);
    float4 b = __ldg((const float4*)beta + lane);
    float4 o4;
    o4.x = (acc.x - mu) * rs * g.x + b.x;
    o4.y = (acc.y - mu) * rs * g.y + b.y;
    o4.z = (acc.z - mu) * rs * g.z + b.z;
    o4.w = (acc.w - mu) * rs * g.w + b.w;

    ((float4*)(g_ln + (size_t)row * D))[lane] = o4;
}

// ---------------------------------------------------------------------------
// 3) masked gather
// ---------------------------------------------------------------------------
__global__ void gather_kernel(const int* __restrict__ x,
                              float* __restrict__ out,
                              int B, int n) {
    int gtid = blockIdx.x * blockDim.x + threadIdx.x;
    int b = gtid >> 5;
    int lane = gtid & 31;
    if (b >= B) return;

    int xv = __ldg(x + b);
    float4 o = make_float4(0.f, 0.f, 0.f, 0.f);
    if (xv >= 1 && xv <= n)
        o = __ldg((const float4*)(g_ln + (size_t)(xv - 1) * D) + lane);
    ((float4*)(out + (size_t)b * D))[lane] = o;
}

// ---------------------------------------------------------------------------
// launch
// ---------------------------------------------------------------------------
extern "C" void kernel_launch(void* const* d_in, const int* in_sizes, int n_in,
                              void* d_out, int out_size) {
    const int*   x     = (const int*)d_in[0];
    const float* emb   = (const float*)d_in[1];
    const float* W     = (const float*)d_in[2];
    const float* bias  = (const float*)d_in[3];
    const float* vals  = (const float*)d_in[4];
    const int*   rows  = (const int*)d_in[5];
    const int*   cols  = (const int*)d_in[6];
    const float* gamma = (const float*)d_in[7];
    const float* beta  = (const float*)d_in[8];
    float* out = (float*)d_out;

    const int B = in_sizes[0];
    const int n = in_sizes[1] / D;
    const int E = in_sizes[4];

    // opt-in to 64KB dynamic smem for the tensor-core GEMM (host-side, idempotent)
    cudaFuncSetAttribute(gemm_tc_kernel,
                         cudaFuncAttributeMaxDynamicSharedMemorySize, 65536);

    // CSR build
    zero_cnt_kernel<<<(n + 1023) / 1024, 1024>>>(n);
    count_kernel<<<1184, 256>>>(rows, E);
    int nb = (n + SCAN_BLK - 1) / SCAN_BLK;
    scan1_kernel<<<nb, SCAN_BLK>>>(n);
    scan2_kernel<<<1, MAX_SCAN_BLOCKS>>>(nb);
    scan3_kernel<<<(n + 255) / 256, 256>>>(n, E);
    scatter_kernel<<<1184, 256>>>(rows, cols, vals, E);

    // dense linear via tensor cores
    int gemm_blocks = (n + GEMM_BLK_M - 1) / GEMM_BLK_M;
    gemm_tc_kernel<<<gemm_blocks, 256, 65536>>>(emb, W, bias, n);

    // fused SpMM + ReLU + LN (warp per row)
    long long t2 = (long long)n * 32;
    spmm_ln_kernel<<<(int)((t2 + 255) / 256), 256>>>(gamma, beta, n);

    // masked gather
    long long t3 = (long long)B * 32;
    gather_kernel<<<(int)((t3 + 255) / 256), 256>>>(x, out, B, n);
}

// round 6
// speedup vs baseline: 2.0836x; 1.2018x over previous
#include <cuda_runtime.h>
#include <cuda_fp16.h>
#include <cstdint>

#define D 128
#define NN_MAX 100000
#define E_MAX  1600000
#define SCAN_BLK 1024
#define MAX_SCAN_BLOCKS 128
#define GEMM_BLK_M 128

// ---------------- device scratch (allocation-free rule) ----------------
__device__ __half g_h16[(size_t)NN_MAX * D];  // GEMM output h (fp16)
__device__ float  g_ln[(size_t)NN_MAX * D];   // LN output (fp32)
__device__ int    g_cnt[NN_MAX];
__device__ int    g_off[NN_MAX + 1];
__device__ int    g_cur[NN_MAX];
__device__ int2   g_edge[E_MAX];              // {col, val-bits}
__device__ int    g_bsum[MAX_SCAN_BLOCKS];

// ---------------------------------------------------------------------------
// CSR build: count -> scan -> scatter
// ---------------------------------------------------------------------------
__global__ void zero_cnt_kernel(int n) {
    int i = blockIdx.x * blockDim.x + threadIdx.x;
    if (i < n) g_cnt[i] = 0;
}

__global__ void count_kernel(const int* __restrict__ rows, int E) {
    int i = blockIdx.x * blockDim.x + threadIdx.x;
    int stride = gridDim.x * blockDim.x;
    int E4 = E >> 2;
    const int4* r4 = (const int4*)rows;
    for (int j = i; j < E4; j += stride) {
        int4 r = __ldg(r4 + j);
        atomicAdd(&g_cnt[r.x], 1);
        atomicAdd(&g_cnt[r.y], 1);
        atomicAdd(&g_cnt[r.z], 1);
        atomicAdd(&g_cnt[r.w], 1);
    }
    // tail
    for (int j = (E4 << 2) + i; j < E; j += stride)
        atomicAdd(&g_cnt[__ldg(rows + j)], 1);
}

__global__ void scan1_kernel(int n) {
    __shared__ int s[SCAN_BLK];
    int t = threadIdx.x;
    int i = blockIdx.x * SCAN_BLK + t;
    int v = (i < n) ? g_cnt[i] : 0;
    s[t] = v;
    __syncthreads();
    #pragma unroll
    for (int off = 1; off < SCAN_BLK; off <<= 1) {
        int add = (t >= off) ? s[t - off] : 0;
        __syncthreads();
        s[t] += add;
        __syncthreads();
    }
    if (i < n) g_off[i] = s[t] - v;
    if (t == SCAN_BLK - 1) g_bsum[blockIdx.x] = s[t];
}

__global__ void scan2_kernel(int nb) {
    __shared__ int s[MAX_SCAN_BLOCKS];
    int t = threadIdx.x;
    int v = (t < nb) ? g_bsum[t] : 0;
    s[t] = v;
    __syncthreads();
    #pragma unroll
    for (int off = 1; off < MAX_SCAN_BLOCKS; off <<= 1) {
        int add = (t >= off) ? s[t - off] : 0;
        __syncthreads();
        s[t] += add;
        __syncthreads();
    }
    if (t < nb) g_bsum[t] = s[t] - v;
}

__global__ void scan3_kernel(int n, int E) {
    int i = blockIdx.x * blockDim.x + threadIdx.x;
    if (i < n) {
        int o = g_off[i] + g_bsum[i / SCAN_BLK];
        g_off[i] = o;
        g_cur[i] = o;
    }
    if (i == 0) g_off[n] = E;
}

__global__ void scatter_kernel(const int* __restrict__ rows,
                               const int* __restrict__ cols,
                               const float* __restrict__ vals,
                               int E) {
    int i = blockIdx.x * blockDim.x + threadIdx.x;
    int stride = gridDim.x * blockDim.x;
    for (; i < E; i += stride) {
        int r = __ldg(rows + i);
        int p = atomicAdd(&g_cur[r], 1);
        g_edge[p] = make_int2(__ldg(cols + i), __float_as_int(__ldg(vals + i)));
    }
}

// ---------------------------------------------------------------------------
// 1) h = emb @ W + bias  — tf32 tensor-core GEMM (mma.sync m16n8k8), fp16 out
// ---------------------------------------------------------------------------
__device__ __forceinline__ uint32_t f2tf32(float f) {
    uint32_t u;
    asm("cvt.rna.tf32.f32 %0, %1;" : "=r"(u) : "f"(f));
    return u;
}

__global__ void __launch_bounds__(256, 2)
gemm_tc_kernel(const float* __restrict__ emb,
               const float* __restrict__ W,
               const float* __restrict__ bias,
               int n) {
    extern __shared__ float2 s_w[];        // 8192 float2 = 64KB
    const int tid  = threadIdx.x;
    const int lane = tid & 31;
    const int warp = tid >> 5;             // 0..7
    const int tg   = lane & 3;
    const int grp  = lane >> 2;

    // stage W as packed tf32 pairs (W[k][n], W[k+4][n])
    #pragma unroll
    for (int i = tid; i < 8192; i += 256) {
        int s   = i >> 9;
        int rem = i & 511;
        int nn  = rem >> 2;
        int t   = rem & 3;
        int k0  = s * 8 + t;
        float w0 = __ldg(W + k0 * D + nn);
        float w1 = __ldg(W + (k0 + 4) * D + nn);
        s_w[i] = make_float2(__uint_as_float(f2tf32(w0)), __uint_as_float(f2tf32(w1)));
    }
    __syncthreads();

    const int row0 = blockIdx.x * GEMM_BLK_M + warp * 16 + grp;
    const int row1 = row0 + 8;
    const bool v0 = row0 < n;
    const bool v1 = row1 < n;
    const float* a0p = emb + (size_t)(v0 ? row0 : 0) * D;
    const float* a1p = emb + (size_t)(v1 ? row1 : 0) * D;

    float c[16][4];
    #pragma unroll
    for (int nf = 0; nf < 16; nf++)
        c[nf][0] = c[nf][1] = c[nf][2] = c[nf][3] = 0.f;

    #pragma unroll
    for (int s = 0; s < 16; s++) {
        int k = s * 8 + tg;
        uint32_t a0 = 0, a1 = 0, a2 = 0, a3 = 0;
        if (v0) { a0 = f2tf32(__ldg(a0p + k)); a2 = f2tf32(__ldg(a0p + k + 4)); }
        if (v1) { a1 = f2tf32(__ldg(a1p + k)); a3 = f2tf32(__ldg(a1p + k + 4)); }

        const float2* wp = s_w + (s << 9) + (grp << 2) + tg;
        #pragma unroll
        for (int nf = 0; nf < 16; nf++) {
            float2 b = wp[nf << 5];
            uint32_t b0 = __float_as_uint(b.x);
            uint32_t b1 = __float_as_uint(b.y);
            asm volatile(
                "mma.sync.aligned.m16n8k8.row.col.f32.tf32.tf32.f32 "
                "{%0,%1,%2,%3}, {%4,%5,%6,%7}, {%8,%9}, {%0,%1,%2,%3};"
                : "+f"(c[nf][0]), "+f"(c[nf][1]), "+f"(c[nf][2]), "+f"(c[nf][3])
                : "r"(a0), "r"(a1), "r"(a2), "r"(a3), "r"(b0), "r"(b1));
        }
    }

    // epilogue: bias in fp32, store as half2
    #pragma unroll
    for (int nf = 0; nf < 16; nf++) {
        int col = (nf << 3) + (tg << 1);
        float2 b2 = __ldg((const float2*)(bias + col));
        if (v0) {
            __half2 o = __floats2half2_rn(c[nf][0] + b2.x, c[nf][1] + b2.y);
            *(__half2*)(g_h16 + (size_t)row0 * D + col) = o;
        }
        if (v1) {
            __half2 o = __floats2half2_rn(c[nf][2] + b2.x, c[nf][3] + b2.y);
            *(__half2*)(g_h16 + (size_t)row1 * D + col) = o;
        }
    }
}

// ---------------------------------------------------------------------------
// 2) fused SpMM (warp per row, fp16 h reads, fp32 accum) + ReLU + LayerNorm
// ---------------------------------------------------------------------------
__global__ void spmm_ln_kernel(const float* __restrict__ gamma,
                               const float* __restrict__ beta,
                               int n) {
    int gtid = blockIdx.x * blockDim.x + threadIdx.x;
    int row = gtid >> 5;
    int lane = gtid & 31;
    if (row >= n) return;

    int s   = g_off[row];
    int end = g_off[row + 1];

    float4 acc = make_float4(0.f, 0.f, 0.f, 0.f);
    for (int base = s; base < end; base += 32) {
        int m = min(32, end - base);
        int2 ev = make_int2(0, 0);
        if (lane < m) ev = __ldg(g_edge + base + lane);
        #pragma unroll 8
        for (int j = 0; j < m; j++) {
            int   cj = __shfl_sync(0xffffffffu, ev.x, j);
            float vj = __int_as_float(__shfl_sync(0xffffffffu, ev.y, j));
            // lane covers cols [4*lane, 4*lane+4): two half2 = 8 bytes
            uint2 hbits = __ldg((const uint2*)(g_h16 + (size_t)cj * D) + lane);
            float2 h01 = __half22float2(*(__half2*)&hbits.x);
            float2 h23 = __half22float2(*(__half2*)&hbits.y);
            acc.x = fmaf(vj, h01.x, acc.x);
            acc.y = fmaf(vj, h01.y, acc.y);
            acc.z = fmaf(vj, h23.x, acc.z);
            acc.w = fmaf(vj, h23.y, acc.w);
        }
    }

    // ReLU
    acc.x = fmaxf(acc.x, 0.f);
    acc.y = fmaxf(acc.y, 0.f);
    acc.z = fmaxf(acc.z, 0.f);
    acc.w = fmaxf(acc.w, 0.f);

    // LayerNorm over 128
    float sum = acc.x + acc.y + acc.z + acc.w;
    float ssq = acc.x * acc.x + acc.y * acc.y + acc.z * acc.z + acc.w * acc.w;
    #pragma unroll
    for (int o = 16; o > 0; o >>= 1) {
        sum += __shfl_xor_sync(0xffffffffu, sum, o);
        ssq += __shfl_xor_sync(0xffffffffu, ssq, o);
    }
    const float inv_d = 1.f / 128.f;
    float mu  = sum * inv_d;
    float var = ssq * inv_d - mu * mu;
    float rs  = rsqrtf(var + 1e-5f);

    float4 g = __ldg((const float4*)gamma + lane);
    float4 b = __ldg((const float4*)beta + lane);
    float4 o4;
    o4.x = (acc.x - mu) * rs * g.x + b.x;
    o4.y = (acc.y - mu) * rs * g.y + b.y;
    o4.z = (acc.z - mu) * rs * g.z + b.z;
    o4.w = (acc.w - mu) * rs * g.w + b.w;

    ((float4*)(g_ln + (size_t)row * D))[lane] = o4;
}

// ---------------------------------------------------------------------------
// 3) masked gather (streaming stores: keep g_ln L2-resident)
// ---------------------------------------------------------------------------
__global__ void gather_kernel(const int* __restrict__ x,
                              float* __restrict__ out,
                              int B, int n) {
    int gtid = blockIdx.x * blockDim.x + threadIdx.x;
    int b = gtid >> 5;
    int lane = gtid & 31;
    if (b >= B) return;

    int xv = __ldg(x + b);
    float4 o = make_float4(0.f, 0.f, 0.f, 0.f);
    if (xv >= 1 && xv <= n)
        o = __ldg((const float4*)(g_ln + (size_t)(xv - 1) * D) + lane);
    __stcs((float4*)(out + (size_t)b * D) + lane, o);
}

// ---------------------------------------------------------------------------
// launch
// ---------------------------------------------------------------------------
extern "C" void kernel_launch(void* const* d_in, const int* in_sizes, int n_in,
                              void* d_out, int out_size) {
    const int*   x     = (const int*)d_in[0];
    const float* emb   = (const float*)d_in[1];
    const float* W     = (const float*)d_in[2];
    const float* bias  = (const float*)d_in[3];
    const float* vals  = (const float*)d_in[4];
    const int*   rows  = (const int*)d_in[5];
    const int*   cols  = (const int*)d_in[6];
    const float* gamma = (const float*)d_in[7];
    const float* beta  = (const float*)d_in[8];
    float* out = (float*)d_out;

    const int B = in_sizes[0];
    const int n = in_sizes[1] / D;
    const int E = in_sizes[4];

    cudaFuncSetAttribute(gemm_tc_kernel,
                         cudaFuncAttributeMaxDynamicSharedMemorySize, 65536);

    // CSR build
    zero_cnt_kernel<<<(n + 1023) / 1024, 1024>>>(n);
    count_kernel<<<1184, 256>>>(rows, E);
    int nb = (n + SCAN_BLK - 1) / SCAN_BLK;
    scan1_kernel<<<nb, SCAN_BLK>>>(n);
    scan2_kernel<<<1, MAX_SCAN_BLOCKS>>>(nb);
    scan3_kernel<<<(n + 255) / 256, 256>>>(n, E);
    scatter_kernel<<<1184, 256>>>(rows, cols, vals, E);

    // dense linear via tensor cores
    int gemm_blocks = (n + GEMM_BLK_M - 1) / GEMM_BLK_M;
    gemm_tc_kernel<<<gemm_blocks, 256, 65536>>>(emb, W, bias, n);

    // fused SpMM + ReLU + LN (warp per row)
    long long t2 = (long long)n * 32;
    spmm_ln_kernel<<<(int)((t2 + 255) / 256), 256>>>(gamma, beta, n);

    // masked gather
    long long t3 = (long long)B * 32;
    gather_kernel<<<(int)((t3 + 255) / 256), 256>>>(x, out, B, n);
}